// round 1
// baseline (speedup 1.0000x reference)
#include <cuda_runtime.h>
#include <math.h>

#define B_  2
#define T_  2048
#define C_  1024
#define H_  16
#define HD_ 64
#define M_  (B_*T_)

// Scratch (device globals: allocation-free)
__device__ float g_Q[B_*H_*T_*HD_];
__device__ float g_K[B_*H_*T_*HD_];
__device__ float g_V[B_*H_*T_*HD_];
__device__ float g_Y[B_*T_*C_];

// ----------------------------------------------------------------------------
// Tiled SGEMM: C[M,N] = A[M,K] * W[K,N] + bias[N]
// BM=128, BN=64, BK=16, 256 threads, 8x4 micro-tile per thread.
// to_heads=1 -> scatter output into [B,H,T,HD] layout.
// ----------------------------------------------------------------------------
#define BM  128
#define BN  64
#define BKK 16

__global__ __launch_bounds__(256) void gemm_kernel(
    const float* __restrict__ A, const float* __restrict__ W,
    const float* __restrict__ bias, float* __restrict__ Cout, int to_heads)
{
    const int K = C_, N = C_;
    __shared__ float As[BKK][BM + 4];   // k-major, padded
    __shared__ float Bs[BKK][BN];

    int tid = threadIdx.x;
    int bm = blockIdx.y * BM;
    int bn = blockIdx.x * BN;
    int tx = tid & 15;        // N direction (16 x 4 = 64)
    int ty = tid >> 4;        // M direction (16 x 8 = 128)

    float acc[8][4];
    #pragma unroll
    for (int i = 0; i < 8; i++)
        #pragma unroll
        for (int j = 0; j < 4; j++) acc[i][j] = 0.f;

    for (int k0 = 0; k0 < K; k0 += BKK) {
        // A tile 128x16 -> smem transposed (k-major). 512 float4 loads.
        #pragma unroll
        for (int i = 0; i < 2; i++) {
            int idx = tid + i * 256;
            int r  = idx >> 2;            // 0..127
            int c4 = (idx & 3) * 4;       // 0,4,8,12
            float4 v = *(const float4*)(A + (size_t)(bm + r) * K + k0 + c4);
            As[c4 + 0][r] = v.x;
            As[c4 + 1][r] = v.y;
            As[c4 + 2][r] = v.z;
            As[c4 + 3][r] = v.w;
        }
        // B tile 16x64. 256 float4 loads.
        {
            int r  = tid >> 4;            // 0..15
            int c4 = (tid & 15) * 4;      // 0..60
            *(float4*)&Bs[r][c4] = *(const float4*)(W + (size_t)(k0 + r) * N + bn + c4);
        }
        __syncthreads();

        #pragma unroll
        for (int k = 0; k < BKK; k++) {
            float4 a0 = *(float4*)&As[k][ty * 8];
            float4 a1 = *(float4*)&As[k][ty * 8 + 4];
            float4 b0 = *(float4*)&Bs[k][tx * 4];
            float a[8] = {a0.x, a0.y, a0.z, a0.w, a1.x, a1.y, a1.z, a1.w};
            float b[4] = {b0.x, b0.y, b0.z, b0.w};
            #pragma unroll
            for (int i = 0; i < 8; i++)
                #pragma unroll
                for (int j = 0; j < 4; j++)
                    acc[i][j] = fmaf(a[i], b[j], acc[i][j]);
        }
        __syncthreads();
    }

    // Store (+bias)
    #pragma unroll
    for (int i = 0; i < 8; i++) {
        int m = bm + ty * 8 + i;
        int bb = m / T_, t = m % T_;
        if (to_heads) {
            #pragma unroll
            for (int j = 0; j < 4; j++) {
                int n = bn + tx * 4 + j;
                int h = n >> 6, d = n & 63;
                Cout[(((size_t)bb * H_ + h) * T_ + t) * HD_ + d] = acc[i][j] + bias[n];
            }
        } else {
            int n = bn + tx * 4;
            float4 r = make_float4(acc[i][0] + bias[n + 0], acc[i][1] + bias[n + 1],
                                   acc[i][2] + bias[n + 2], acc[i][3] + bias[n + 3]);
            *(float4*)&Cout[(size_t)m * C_ + n] = r;
        }
    }
}

// ----------------------------------------------------------------------------
// Flash attention (causal): one block per (b, h, 64-query tile).
// 256 threads: 4x4 micro-tile per thread for both S = QK^T and O += P V.
// Q,K,V in [B,H,T,HD]; Y written in [B,T,C].
// Dynamic smem layout (floats):
//   Qs [64][68]  d-major  (Qs[d][m])
//   Ks [64][68]  d-major  (Ks[d][n])
//   Vs [64][64]  natural  (Vs[n][d])
//   Ps [64][68]  n-major  (Ps[n][m])
// ----------------------------------------------------------------------------
#define SMEM_ATTN ((3 * 64 * 68 + 64 * 64) * 4)

__global__ __launch_bounds__(256) void attn_kernel(
    const float* __restrict__ Q, const float* __restrict__ K,
    const float* __restrict__ V, float* __restrict__ Y)
{
    extern __shared__ float sm[];
    float* Qs = sm;                       // 64*68
    float* Ks = sm + 64 * 68;             // 64*68
    float* Vs = sm + 2 * 64 * 68;         // 64*64
    float* Ps = sm + 2 * 64 * 68 + 64 * 64; // 64*68

    int tid = threadIdx.x;
    int tx = tid & 15;   // n / d direction (16 x 4 = 64)
    int ty = tid >> 4;   // m direction     (16 x 4 = 64)
    int qt = blockIdx.x, h = blockIdx.y, b = blockIdx.z;

    const size_t headbase = ((size_t)b * H_ + h) * T_;
    const float* Qb = Q + (headbase + (size_t)qt * 64) * HD_;

    // Load Q tile transposed (d-major)
    #pragma unroll
    for (int i = 0; i < 4; i++) {
        int idx = tid + i * 256;
        int m  = idx >> 4;
        int d4 = (idx & 15) * 4;
        float4 v = *(const float4*)(Qb + m * HD_ + d4);
        Qs[(d4 + 0) * 68 + m] = v.x;
        Qs[(d4 + 1) * 68 + m] = v.y;
        Qs[(d4 + 2) * 68 + m] = v.z;
        Qs[(d4 + 3) * 68 + m] = v.w;
    }

    float o[4][4];
    #pragma unroll
    for (int i = 0; i < 4; i++)
        #pragma unroll
        for (int j = 0; j < 4; j++) o[i][j] = 0.f;
    float mrow[4] = {-3.0e38f, -3.0e38f, -3.0e38f, -3.0e38f};
    float lrow[4] = {0.f, 0.f, 0.f, 0.f};
    const float scale = 0.125f;  // 1/sqrt(64)

    for (int kt = 0; kt <= qt; kt++) {
        __syncthreads();  // previous PV done before K/V/P smem reuse
        const float* Kb = K + (headbase + (size_t)kt * 64) * HD_;
        const float* Vb = V + (headbase + (size_t)kt * 64) * HD_;
        #pragma unroll
        for (int i = 0; i < 4; i++) {
            int idx = tid + i * 256;
            int n  = idx >> 4;
            int d4 = (idx & 15) * 4;
            float4 v = *(const float4*)(Kb + n * HD_ + d4);
            Ks[(d4 + 0) * 68 + n] = v.x;
            Ks[(d4 + 1) * 68 + n] = v.y;
            Ks[(d4 + 2) * 68 + n] = v.z;
            Ks[(d4 + 3) * 68 + n] = v.w;
            *(float4*)&Vs[n * 64 + d4] = *(const float4*)(Vb + n * HD_ + d4);
        }
        __syncthreads();

        // S = Q K^T (4x4 per thread)
        float s[4][4];
        #pragma unroll
        for (int i = 0; i < 4; i++)
            #pragma unroll
            for (int j = 0; j < 4; j++) s[i][j] = 0.f;
        #pragma unroll 4
        for (int d = 0; d < 64; d++) {
            float4 a4 = *(float4*)&Qs[d * 68 + ty * 4];
            float4 b4 = *(float4*)&Ks[d * 68 + tx * 4];
            float a[4] = {a4.x, a4.y, a4.z, a4.w};
            float bv[4] = {b4.x, b4.y, b4.z, b4.w};
            #pragma unroll
            for (int i = 0; i < 4; i++)
                #pragma unroll
                for (int j = 0; j < 4; j++)
                    s[i][j] = fmaf(a[i], bv[j], s[i][j]);
        }

        bool diag = (kt == qt);
        // online softmax per row (16 lanes share a row-group; reduce via shfl)
        #pragma unroll
        for (int i = 0; i < 4; i++) {
            int qg = qt * 64 + ty * 4 + i;
            float rmax = -1e30f;
            #pragma unroll
            for (int j = 0; j < 4; j++) {
                float sv = s[i][j] * scale;
                if (diag && (kt * 64 + tx * 4 + j) > qg) sv = -1e30f;
                s[i][j] = sv;
                rmax = fmaxf(rmax, sv);
            }
            #pragma unroll
            for (int off = 8; off > 0; off >>= 1)
                rmax = fmaxf(rmax, __shfl_xor_sync(0xffffffffu, rmax, off));
            float newm = fmaxf(mrow[i], rmax);
            float corr = __expf(mrow[i] - newm);
            mrow[i] = newm;
            float rsum = 0.f;
            #pragma unroll
            for (int j = 0; j < 4; j++) {
                float p = __expf(s[i][j] - newm);
                s[i][j] = p;
                rsum += p;
            }
            #pragma unroll
            for (int off = 8; off > 0; off >>= 1)
                rsum += __shfl_xor_sync(0xffffffffu, rsum, off);
            lrow[i] = lrow[i] * corr + rsum;
            #pragma unroll
            for (int j = 0; j < 4; j++) o[i][j] *= corr;
        }

        // P -> smem transposed (n-major) for the PV pass
        #pragma unroll
        for (int j = 0; j < 4; j++)
            #pragma unroll
            for (int i = 0; i < 4; i++)
                Ps[(tx * 4 + j) * 68 + ty * 4 + i] = s[i][j];
        __syncthreads();

        // O += P V
        #pragma unroll 4
        for (int n = 0; n < 64; n++) {
            float4 a4 = *(float4*)&Ps[n * 68 + ty * 4];
            float4 v4 = *(float4*)&Vs[n * 64 + tx * 4];
            float a[4] = {a4.x, a4.y, a4.z, a4.w};
            float vv[4] = {v4.x, v4.y, v4.z, v4.w};
            #pragma unroll
            for (int i = 0; i < 4; i++)
                #pragma unroll
                for (int j = 0; j < 4; j++)
                    o[i][j] = fmaf(a[i], vv[j], o[i][j]);
        }
    }

    // finalize: Y[b][q][h*64+d] = O/l
    #pragma unroll
    for (int i = 0; i < 4; i++) {
        float inv = 1.0f / lrow[i];
        int q = qt * 64 + ty * 4 + i;
        float4 r = make_float4(o[i][0] * inv, o[i][1] * inv, o[i][2] * inv, o[i][3] * inv);
        *(float4*)&Y[((size_t)b * T_ + q) * C_ + h * 64 + tx * 4] = r;
    }
}

// ----------------------------------------------------------------------------
extern "C" void kernel_launch(void* const* d_in, const int* in_sizes, int n_in,
                              void* d_out, int out_size)
{
    const float* x  = (const float*)d_in[0];
    const float* Wq = (const float*)d_in[1];
    const float* bq = (const float*)d_in[2];
    const float* Wk = (const float*)d_in[3];
    const float* bk = (const float*)d_in[4];
    const float* Wv = (const float*)d_in[5];
    const float* bv = (const float*)d_in[6];
    const float* Wp = (const float*)d_in[7];
    const float* bp = (const float*)d_in[8];

    float *Qp, *Kp, *Vp, *Yp;
    cudaGetSymbolAddress((void**)&Qp, g_Q);
    cudaGetSymbolAddress((void**)&Kp, g_K);
    cudaGetSymbolAddress((void**)&Vp, g_V);
    cudaGetSymbolAddress((void**)&Yp, g_Y);

    cudaFuncSetAttribute(attn_kernel, cudaFuncAttributeMaxDynamicSharedMemorySize, SMEM_ATTN);

    dim3 ggrid(C_ / BN, M_ / BM);   // (16, 32)
    gemm_kernel<<<ggrid, 256>>>(x, Wq, bq, Qp, 1);
    gemm_kernel<<<ggrid, 256>>>(x, Wk, bk, Kp, 1);
    gemm_kernel<<<ggrid, 256>>>(x, Wv, bv, Vp, 1);

    attn_kernel<<<dim3(T_ / 64, H_, B_), 256, SMEM_ATTN>>>(Qp, Kp, Vp, Yp);

    gemm_kernel<<<ggrid, 256>>>(Yp, Wp, bp, (float*)d_out, 0);
}

// round 3
// speedup vs baseline: 3.3808x; 3.3808x over previous
#include <cuda_runtime.h>
#include <math.h>
#include <stdint.h>

#define B_  2
#define T_  2048
#define C_  1024
#define H_  16
#define HD_ 64
#define M_  (B_*T_)

// Scratch (device globals: allocation-free)
__device__ float g_X[M_*C_];          // tf32-rounded x
__device__ float g_W4[4*C_*C_];       // tf32-rounded Wq,Wk,Wv,Wp
__device__ float g_Q[B_*H_*T_*HD_];
__device__ float g_K[B_*H_*T_*HD_];
__device__ float g_V[B_*H_*T_*HD_];
__device__ float g_Y[M_*C_];

// ============================================================================
// helpers (baseline PTX ISA only: mma.sync + cp.async, no 'a' features)
// ============================================================================
__device__ __forceinline__ uint32_t smem_u32(const void* p) {
    uint32_t a;
    asm("{ .reg .u64 t; cvta.to.shared.u64 t, %1; cvt.u32.u64 %0, t; }" : "=r"(a) : "l"(p));
    return a;
}
__device__ __forceinline__ uint32_t cvt_tf32(float x) {
    uint32_t r; asm("cvt.rna.tf32.f32 %0, %1;" : "=r"(r) : "f"(x)); return r;
}
__device__ __forceinline__ float cvt_tf32f(float x) { return __uint_as_float(cvt_tf32(x)); }

__device__ __forceinline__ void cp16(uint32_t dst, const void* src) {
    asm volatile("cp.async.ca.shared.global [%0], [%1], 16;" :: "r"(dst), "l"(src));
}
#define CP_COMMIT() asm volatile("cp.async.commit_group;")
#define CP_WAIT1()  asm volatile("cp.async.wait_group 1;")
#define CP_WAIT0()  asm volatile("cp.async.wait_group 0;")

// m16n8k8 tf32 mma: A row-major (4 regs), B col-major (2 regs), C f32 (4 regs)
__device__ __forceinline__ void mma8(float* c, const uint32_t* a, const uint32_t* b) {
    asm volatile(
        "mma.sync.aligned.m16n8k8.row.col.f32.tf32.tf32.f32 "
        "{%0,%1,%2,%3}, {%4,%5,%6,%7}, {%8,%9}, {%0,%1,%2,%3};"
        : "+f"(c[0]), "+f"(c[1]), "+f"(c[2]), "+f"(c[3])
        : "r"(a[0]), "r"(a[1]), "r"(a[2]), "r"(a[3]), "r"(b[0]), "r"(b[1]));
}

// ============================================================================
// tf32 pre-round pass (so mma's internal truncation is exact)
// ============================================================================
__global__ void round_tf32_k(const float4* __restrict__ src, float4* __restrict__ dst, int n4) {
    int i = blockIdx.x * blockDim.x + threadIdx.x;
    if (i < n4) {
        float4 v = src[i];
        v.x = cvt_tf32f(v.x); v.y = cvt_tf32f(v.y);
        v.z = cvt_tf32f(v.z); v.w = cvt_tf32f(v.w);
        dst[i] = v;
    }
}

// ============================================================================
// GEMM (tf32 mma): C[M,1024] = A[M,1024] @ W[1024,1024] + bias
// Block 128x128, 8 warps (4m x 2n), warp 32x64. k-tile 32, double-buffered.
// mode 1: scatter to [B,H,T,HD] + tf32-round; mode 0: plain f32 out.
// ============================================================================
#define AP 36     // A smem pitch (floats)
#define BP 136    // B smem pitch (floats)
#define GEMM_BUF (128*AP + 32*BP)           // floats per buffer = 8960
#define GSM (2 * GEMM_BUF * 4)              // 71680 bytes

__global__ __launch_bounds__(256) void gemm_tc(
    const float* __restrict__ A, const float* __restrict__ W,
    const float* __restrict__ bias, float* __restrict__ Cout, int mode)
{
    extern __shared__ float sm[];
    uint32_t smb = smem_u32(sm);
    int tid = threadIdx.x, lane = tid & 31, wid = tid >> 5;
    int wm = wid & 3, wn = wid >> 2;
    int gg = lane >> 2, tt = lane & 3;
    int bm = blockIdx.y * 128, bn = blockIdx.x * 128;

    float acc[2][8][4];
    #pragma unroll
    for (int mt = 0; mt < 2; mt++)
        #pragma unroll
        for (int nt = 0; nt < 8; nt++)
            #pragma unroll
            for (int j = 0; j < 4; j++) acc[mt][nt][j] = 0.f;

    auto load_tiles = [&](int bsel, int kt) {
        int k0 = kt * 32;
        uint32_t abase = smb + bsel * GEMM_BUF * 4;
        uint32_t bbase = abase + 128 * AP * 4;
        #pragma unroll
        for (int i = 0; i < 4; i++) {
            int idx = tid + i * 256;
            int r = idx >> 3, s = (idx & 7) * 4;
            cp16(abase + (uint32_t)(r * AP + s) * 4, A + (size_t)(bm + r) * C_ + k0 + s);
        }
        #pragma unroll
        for (int i = 0; i < 4; i++) {
            int idx = tid + i * 256;
            int r = idx >> 5, s = (idx & 31) * 4;
            cp16(bbase + (uint32_t)(r * BP + s) * 4, W + (size_t)(k0 + r) * C_ + bn + s);
        }
    };

    load_tiles(0, 0); CP_COMMIT();

    for (int kt = 0; kt < 32; kt++) {
        int bsel = kt & 1;
        if (kt < 31) { load_tiles(bsel ^ 1, kt + 1); CP_COMMIT(); CP_WAIT1(); }
        else         { CP_WAIT0(); }
        __syncthreads();

        const uint32_t* Asb = (const uint32_t*)(sm + bsel * GEMM_BUF);
        const uint32_t* Bsb = Asb + 128 * AP;
        #pragma unroll
        for (int ks = 0; ks < 4; ks++) {
            uint32_t af[2][4], bf[8][2];
            #pragma unroll
            for (int mt = 0; mt < 2; mt++) {
                int row = wm * 32 + mt * 16 + gg;
                int c = ks * 8 + tt;
                af[mt][0] = Asb[row * AP + c];
                af[mt][1] = Asb[(row + 8) * AP + c];
                af[mt][2] = Asb[row * AP + c + 4];
                af[mt][3] = Asb[(row + 8) * AP + c + 4];
            }
            #pragma unroll
            for (int nt = 0; nt < 8; nt++) {
                int col = wn * 64 + nt * 8 + gg;
                bf[nt][0] = Bsb[(ks * 8 + tt) * BP + col];
                bf[nt][1] = Bsb[(ks * 8 + tt + 4) * BP + col];
            }
            #pragma unroll
            for (int mt = 0; mt < 2; mt++)
                #pragma unroll
                for (int nt = 0; nt < 8; nt++)
                    mma8(acc[mt][nt], af[mt], bf[nt]);
        }
        __syncthreads();
    }

    // epilogue
    #pragma unroll
    for (int mt = 0; mt < 2; mt++) {
        int m0 = bm + wm * 32 + mt * 16;
        #pragma unroll
        for (int nt = 0; nt < 8; nt++) {
            int col = bn + wn * 64 + nt * 8 + 2 * tt;
            float b0v = bias[col], b1v = bias[col + 1];
            #pragma unroll
            for (int half = 0; half < 2; half++) {
                int m = m0 + gg + half * 8;
                float v0 = acc[mt][nt][half * 2 + 0] + b0v;
                float v1 = acc[mt][nt][half * 2 + 1] + b1v;
                if (mode == 1) {
                    v0 = cvt_tf32f(v0); v1 = cvt_tf32f(v1);
                    int bb = m >> 11, t = m & (T_ - 1);
                    int h = col >> 6, d = col & 63;
                    float2* dst = (float2*)&Cout[(((size_t)bb * H_ + h) * T_ + t) * HD_ + d];
                    *dst = make_float2(v0, v1);
                } else {
                    *(float2*)&Cout[(size_t)m * C_ + col] = make_float2(v0, v1);
                }
            }
        }
    }
}

// ============================================================================
// Flash attention (causal) with tf32 mma.
// Block: 128 queries x (b,h). 8 warps, each warp 16 q-rows, full 64-key tile.
// Q frags register-resident; K/V cp.async double-buffered; P staged per-warp smem.
// ============================================================================
#define QP 68
#define KVP 68
#define SM_PQ 0
#define SM_KV (128 * QP)                  // 8704 floats
#define KV_TILE (64 * KVP)                // 4352 floats
#define KVSTRIDE (2 * KV_TILE)            // K+V per buffer
#define ATTN_SM ((SM_KV + 2 * KVSTRIDE) * 4)   // 104448 bytes

__global__ __launch_bounds__(256, 1) void attn_tc(
    const float* __restrict__ Q, const float* __restrict__ K,
    const float* __restrict__ V, float* __restrict__ Y)
{
    extern __shared__ float sm[];
    uint32_t smb = smem_u32(sm);
    int tid = threadIdx.x, lane = tid & 31, w = tid >> 5;
    int gg = lane >> 2, tt = lane & 3;
    int qt = blockIdx.x, h = blockIdx.y, b = blockIdx.z;
    size_t headbase = ((size_t)b * H_ + h) * T_;
    const float* Qg = Q + (headbase + (size_t)qt * 128) * HD_;

    auto load_kv = [&](int bsel, int kt) {
        uint32_t kb = smb + (uint32_t)(SM_KV + bsel * KVSTRIDE) * 4;
        uint32_t vb = kb + KV_TILE * 4;
        const float* Kg = K + (headbase + (size_t)kt * 64) * HD_;
        const float* Vg = V + (headbase + (size_t)kt * 64) * HD_;
        #pragma unroll
        for (int i = 0; i < 4; i++) {
            int idx = tid + i * 256;
            int r = idx >> 4, s = (idx & 15) * 4;
            cp16(kb + (uint32_t)(r * KVP + s) * 4, Kg + r * HD_ + s);
            cp16(vb + (uint32_t)(r * KVP + s) * 4, Vg + r * HD_ + s);
        }
    };

    // fill Qs and prefetch KV tile 0
    #pragma unroll
    for (int i = 0; i < 8; i++) {
        int idx = tid + i * 256;
        int r = idx >> 4, s = (idx & 15) * 4;
        *(float4*)&sm[SM_PQ + r * QP + s] = *(const float4*)&Qg[r * HD_ + s];
    }
    load_kv(0, 0); CP_COMMIT();
    __syncthreads();

    // Q fragments (register-resident for the whole kernel)
    uint32_t qf[8][4];
    {
        const uint32_t* Qs = (const uint32_t*)&sm[SM_PQ];
        #pragma unroll
        for (int ks = 0; ks < 8; ks++) {
            int row = w * 16 + gg;
            int c = ks * 8 + tt;
            qf[ks][0] = Qs[row * QP + c];
            qf[ks][1] = Qs[(row + 8) * QP + c];
            qf[ks][2] = Qs[row * QP + c + 4];
            qf[ks][3] = Qs[(row + 8) * QP + c + 4];
        }
    }
    __syncthreads();   // all warps done reading Qs; region becomes P staging

    float o[8][4];
    #pragma unroll
    for (int dt = 0; dt < 8; dt++)
        #pragma unroll
        for (int j = 0; j < 4; j++) o[dt][j] = 0.f;
    float mA = -1e30f, mB = -1e30f, lA = 0.f, lB = 0.f;
    int q0w = qt * 128 + w * 16;
    int r0 = q0w + gg, r1 = r0 + 8;
    int ktmax = 2 * qt + 1;
    uint32_t* Ps32 = (uint32_t*)&sm[SM_PQ + w * 16 * QP];

    for (int kt = 0; kt <= ktmax; kt++) {
        int bsel = kt & 1;
        if (kt < ktmax) { load_kv(bsel ^ 1, kt + 1); CP_COMMIT(); CP_WAIT1(); }
        else            { CP_WAIT0(); }
        __syncthreads();

        bool active = (kt * 64) <= (q0w + 15);
        if (active) {
            const uint32_t* Ks = (const uint32_t*)&sm[SM_KV + bsel * KVSTRIDE];
            const uint32_t* Vs = Ks + KV_TILE;

            // S = Q K^T
            float s[8][4];
            #pragma unroll
            for (int nt = 0; nt < 8; nt++)
                #pragma unroll
                for (int j = 0; j < 4; j++) s[nt][j] = 0.f;
            #pragma unroll
            for (int ks = 0; ks < 8; ks++) {
                #pragma unroll
                for (int nt = 0; nt < 8; nt++) {
                    uint32_t bv[2];
                    int row = nt * 8 + gg, c = ks * 8 + tt;
                    bv[0] = Ks[row * KVP + c];
                    bv[1] = Ks[row * KVP + c + 4];
                    mma8(s[nt], qf[ks], bv);
                }
            }

            // scale + causal mask
            bool needmask = (kt * 64 + 63) > q0w;
            #pragma unroll
            for (int nt = 0; nt < 8; nt++) {
                #pragma unroll
                for (int j = 0; j < 4; j++) s[nt][j] *= 0.125f;
                if (needmask) {
                    int c0 = kt * 64 + nt * 8 + 2 * tt;
                    if (c0     > r0) s[nt][0] = -1e30f;
                    if (c0 + 1 > r0) s[nt][1] = -1e30f;
                    if (c0     > r1) s[nt][2] = -1e30f;
                    if (c0 + 1 > r1) s[nt][3] = -1e30f;
                }
            }

            // online softmax (rows r0: regs 0,1 ; r1: regs 2,3)
            float tmA = -1e30f, tmB = -1e30f;
            #pragma unroll
            for (int nt = 0; nt < 8; nt++) {
                tmA = fmaxf(tmA, fmaxf(s[nt][0], s[nt][1]));
                tmB = fmaxf(tmB, fmaxf(s[nt][2], s[nt][3]));
            }
            tmA = fmaxf(tmA, __shfl_xor_sync(0xffffffffu, tmA, 1));
            tmA = fmaxf(tmA, __shfl_xor_sync(0xffffffffu, tmA, 2));
            tmB = fmaxf(tmB, __shfl_xor_sync(0xffffffffu, tmB, 1));
            tmB = fmaxf(tmB, __shfl_xor_sync(0xffffffffu, tmB, 2));
            float nmA = fmaxf(mA, tmA), nmB = fmaxf(mB, tmB);
            float cA = __expf(mA - nmA), cB = __expf(mB - nmB);
            mA = nmA; mB = nmB;
            float sA = 0.f, sB = 0.f;
            #pragma unroll
            for (int nt = 0; nt < 8; nt++) {
                s[nt][0] = __expf(s[nt][0] - nmA);
                s[nt][1] = __expf(s[nt][1] - nmA);
                s[nt][2] = __expf(s[nt][2] - nmB);
                s[nt][3] = __expf(s[nt][3] - nmB);
                sA += s[nt][0] + s[nt][1];
                sB += s[nt][2] + s[nt][3];
            }
            sA += __shfl_xor_sync(0xffffffffu, sA, 1);
            sA += __shfl_xor_sync(0xffffffffu, sA, 2);
            sB += __shfl_xor_sync(0xffffffffu, sB, 1);
            sB += __shfl_xor_sync(0xffffffffu, sB, 2);
            lA = lA * cA + sA;
            lB = lB * cB + sB;
            #pragma unroll
            for (int dt = 0; dt < 8; dt++) {
                o[dt][0] *= cA; o[dt][1] *= cA;
                o[dt][2] *= cB; o[dt][3] *= cB;
            }

            // stage P (tf32-rounded) in per-warp smem
            #pragma unroll
            for (int nt = 0; nt < 8; nt++) {
                int colb = nt * 8 + 2 * tt;
                *(uint2*)&Ps32[gg * QP + colb] =
                    make_uint2(cvt_tf32(s[nt][0]), cvt_tf32(s[nt][1]));
                *(uint2*)&Ps32[(gg + 8) * QP + colb] =
                    make_uint2(cvt_tf32(s[nt][2]), cvt_tf32(s[nt][3]));
            }
            __syncwarp();

            // O += P V
            #pragma unroll
            for (int ks = 0; ks < 8; ks++) {
                uint32_t pa[4];
                int c = ks * 8 + tt;
                pa[0] = Ps32[gg * QP + c];
                pa[1] = Ps32[(gg + 8) * QP + c];
                pa[2] = Ps32[gg * QP + c + 4];
                pa[3] = Ps32[(gg + 8) * QP + c + 4];
                #pragma unroll
                for (int dt = 0; dt < 8; dt++) {
                    uint32_t bv[2];
                    bv[0] = Vs[(ks * 8 + tt) * KVP + dt * 8 + gg];
                    bv[1] = Vs[(ks * 8 + tt + 4) * KVP + dt * 8 + gg];
                    mma8(o[dt], pa, bv);
                }
            }
            __syncwarp();
        }
        __syncthreads();   // all warps done with this KV buffer before overwrite
    }

    // epilogue: Y[b][q][h*64+d], tf32-rounded (feeds final GEMM)
    float iA = 1.f / lA, iB = 1.f / lB;
    size_t yrowA = ((size_t)b * T_ + q0w + gg) * C_ + h * HD_;
    size_t yrowB = yrowA + (size_t)8 * C_;
    #pragma unroll
    for (int dt = 0; dt < 8; dt++) {
        int col = dt * 8 + 2 * tt;
        *(float2*)&Y[yrowA + col] =
            make_float2(cvt_tf32f(o[dt][0] * iA), cvt_tf32f(o[dt][1] * iA));
        *(float2*)&Y[yrowB + col] =
            make_float2(cvt_tf32f(o[dt][2] * iB), cvt_tf32f(o[dt][3] * iB));
    }
}

// ----------------------------------------------------------------------------
extern "C" void kernel_launch(void* const* d_in, const int* in_sizes, int n_in,
                              void* d_out, int out_size)
{
    const float* x  = (const float*)d_in[0];
    const float* Wq = (const float*)d_in[1];
    const float* bq = (const float*)d_in[2];
    const float* Wk = (const float*)d_in[3];
    const float* bk = (const float*)d_in[4];
    const float* Wv = (const float*)d_in[5];
    const float* bv = (const float*)d_in[6];
    const float* Wp = (const float*)d_in[7];
    const float* bp = (const float*)d_in[8];

    float *Xp, *Wp4, *Qp, *Kp, *Vp, *Yp;
    cudaGetSymbolAddress((void**)&Xp, g_X);
    cudaGetSymbolAddress((void**)&Wp4, g_W4);
    cudaGetSymbolAddress((void**)&Qp, g_Q);
    cudaGetSymbolAddress((void**)&Kp, g_K);
    cudaGetSymbolAddress((void**)&Vp, g_V);
    cudaGetSymbolAddress((void**)&Yp, g_Y);

    cudaFuncSetAttribute(gemm_tc, cudaFuncAttributeMaxDynamicSharedMemorySize, GSM);
    cudaFuncSetAttribute(attn_tc, cudaFuncAttributeMaxDynamicSharedMemorySize, ATTN_SM);

    // pre-round operands to tf32 (so mma truncation is exact / unbiased)
    int n4x = M_ * C_ / 4;          // 1M float4
    int n4w = C_ * C_ / 4;          // 256K float4
    round_tf32_k<<<(n4x + 255) / 256, 256>>>((const float4*)x, (float4*)Xp, n4x);
    round_tf32_k<<<(n4w + 255) / 256, 256>>>((const float4*)Wq, (float4*)(Wp4 + 0 * C_ * C_), n4w);
    round_tf32_k<<<(n4w + 255) / 256, 256>>>((const float4*)Wk, (float4*)(Wp4 + 1 * C_ * C_), n4w);
    round_tf32_k<<<(n4w + 255) / 256, 256>>>((const float4*)Wv, (float4*)(Wp4 + 2 * C_ * C_), n4w);
    round_tf32_k<<<(n4w + 255) / 256, 256>>>((const float4*)Wp, (float4*)(Wp4 + 3 * C_ * C_), n4w);

    dim3 ggrid(C_ / 128, M_ / 128);   // (8, 32)
    gemm_tc<<<ggrid, 256, GSM>>>(Xp, Wp4 + 0 * C_ * C_, bq, Qp, 1);
    gemm_tc<<<ggrid, 256, GSM>>>(Xp, Wp4 + 1 * C_ * C_, bk, Kp, 1);
    gemm_tc<<<ggrid, 256, GSM>>>(Xp, Wp4 + 2 * C_ * C_, bv, Vp, 1);

    attn_tc<<<dim3(T_ / 128, H_, B_), 256, ATTN_SM>>>(Qp, Kp, Vp, Yp);

    gemm_tc<<<ggrid, 256, GSM>>>(Yp, Wp4 + 3 * C_ * C_, bp, (float*)d_out, 0);
}

// round 4
// speedup vs baseline: 3.4665x; 1.0254x over previous
#include <cuda_runtime.h>
#include <math.h>
#include <stdint.h>

#define B_  2
#define T_  2048
#define C_  1024
#define H_  16
#define HD_ 64
#define M_  (B_*T_)

// Scratch (device globals: allocation-free)
__device__ float g_X[M_*C_];          // tf32-rounded x
__device__ float g_W4[4*C_*C_];       // tf32-rounded Wq,Wk,Wv,Wp
__device__ float g_Q[B_*H_*T_*HD_];   // pre-scaled by 0.125*log2(e)
__device__ float g_K[B_*H_*T_*HD_];
__device__ float g_V[B_*H_*T_*HD_];
__device__ float g_Y[M_*C_];

#define QSCALE 0.1803368801111731f    /* 0.125 * log2(e) */

// ============================================================================
// helpers (baseline PTX ISA only: mma.sync + cp.async)
// ============================================================================
__device__ __forceinline__ uint32_t smem_u32(const void* p) {
    uint32_t a;
    asm("{ .reg .u64 t; cvta.to.shared.u64 t, %1; cvt.u32.u64 %0, t; }" : "=r"(a) : "l"(p));
    return a;
}
__device__ __forceinline__ uint32_t cvt_tf32(float x) {
    uint32_t r; asm("cvt.rna.tf32.f32 %0, %1;" : "=r"(r) : "f"(x)); return r;
}
__device__ __forceinline__ float cvt_tf32f(float x) { return __uint_as_float(cvt_tf32(x)); }

__device__ __forceinline__ void cp16(uint32_t dst, const void* src) {
    asm volatile("cp.async.ca.shared.global [%0], [%1], 16;" :: "r"(dst), "l"(src));
}
#define CP_COMMIT() asm volatile("cp.async.commit_group;")
#define CP_WAIT1()  asm volatile("cp.async.wait_group 1;")

// m16n8k8 tf32 mma: A row-major (4 regs), B col-major (2 regs), C f32 (4 regs)
__device__ __forceinline__ void mma8(float* c, const uint32_t* a, const uint32_t* b) {
    asm volatile(
        "mma.sync.aligned.m16n8k8.row.col.f32.tf32.tf32.f32 "
        "{%0,%1,%2,%3}, {%4,%5,%6,%7}, {%8,%9}, {%0,%1,%2,%3};"
        : "+f"(c[0]), "+f"(c[1]), "+f"(c[2]), "+f"(c[3])
        : "r"(a[0]), "r"(a[1]), "r"(a[2]), "r"(a[3]), "r"(b[0]), "r"(b[1]));
}

// ============================================================================
// fused tf32 pre-round: segment 0 = x (1M float4), 1..4 = W's (256K float4 each)
// ============================================================================
#define N4X (M_*C_/4)
#define N4W (C_*C_/4)
__global__ void round_all_k(const float4* __restrict__ x, float4* __restrict__ X,
                            const float4* __restrict__ w0, const float4* __restrict__ w1,
                            const float4* __restrict__ w2, const float4* __restrict__ w3,
                            float4* __restrict__ W4)
{
    long i = (long)blockIdx.x * blockDim.x + threadIdx.x;
    const float4* src; float4* dst;
    if (i < N4X) { src = x + i; dst = X + i; }
    else {
        long j = i - N4X;
        int seg = (int)(j >> 18);          // /262144
        long off = j & (N4W - 1);
        const float4* ws[4] = {w0, w1, w2, w3};
        src = ws[seg] + off;
        dst = W4 + (long)seg * N4W + off;
    }
    float4 v = *src;
    v.x = cvt_tf32f(v.x); v.y = cvt_tf32f(v.y);
    v.z = cvt_tf32f(v.z); v.w = cvt_tf32f(v.w);
    *dst = v;
}

// ============================================================================
// GEMM (tf32 mma): 128x128 block tile, 8 warps (4m x 2n), k-tile 32,
// 3-stage cp.async pipeline (ONE syncthreads per k-tile).
// blockIdx.z selects (W, bias, dst). mode: 0 plain, 1 head-scatter+round,
// 2 head-scatter+round+QSCALE.
// ============================================================================
#define AP 36
#define BP 136
#define GEMM_BUF (128*AP + 32*BP)           // 8960 floats per buffer
#define GSM (3 * GEMM_BUF * 4)              // 107520 bytes

__global__ __launch_bounds__(256) void gemm_tc(
    const float* __restrict__ A,
    const float* __restrict__ W0, const float* __restrict__ W1, const float* __restrict__ W2,
    const float* __restrict__ b0, const float* __restrict__ b1, const float* __restrict__ b2,
    float* __restrict__ D0, float* __restrict__ D1, float* __restrict__ D2,
    int mode0)
{
    extern __shared__ float sm[];
    uint32_t smb = smem_u32(sm);
    int tid = threadIdx.x, lane = tid & 31, wid = tid >> 5;
    int wm = wid & 3, wn = wid >> 2;
    int gg = lane >> 2, tt = lane & 3;
    int bm = blockIdx.y * 128, bn = blockIdx.x * 128;
    int z = blockIdx.z;

    const float* W; const float* bias; float* Cout; int mode;
    if (z == 0)      { W = W0; bias = b0; Cout = D0; mode = mode0; }
    else if (z == 1) { W = W1; bias = b1; Cout = D1; mode = 1; }
    else             { W = W2; bias = b2; Cout = D2; mode = 1; }

    float acc[2][8][4];
    #pragma unroll
    for (int mt = 0; mt < 2; mt++)
        #pragma unroll
        for (int nt = 0; nt < 8; nt++)
            #pragma unroll
            for (int j = 0; j < 4; j++) acc[mt][nt][j] = 0.f;

    auto load_tiles = [&](int bsel, int kt) {
        int k0 = kt * 32;
        uint32_t abase = smb + bsel * GEMM_BUF * 4;
        uint32_t bbase = abase + 128 * AP * 4;
        #pragma unroll
        for (int i = 0; i < 4; i++) {
            int idx = tid + i * 256;
            int r = idx >> 3, s = (idx & 7) * 4;
            cp16(abase + (uint32_t)(r * AP + s) * 4, A + (size_t)(bm + r) * C_ + k0 + s);
        }
        #pragma unroll
        for (int i = 0; i < 4; i++) {
            int idx = tid + i * 256;
            int r = idx >> 5, s = (idx & 31) * 4;
            cp16(bbase + (uint32_t)(r * BP + s) * 4, W + (size_t)(k0 + r) * C_ + bn + s);
        }
    };

    load_tiles(0, 0); CP_COMMIT();
    load_tiles(1, 1); CP_COMMIT();

    int cur = 0, nxt2 = 2;   // buffer indices mod 3
    for (int kt = 0; kt < 32; kt++) {
        CP_WAIT1();                   // group kt complete (in-order completion)
        __syncthreads();              // also: everyone done with buf (kt-1)%3
        if (kt + 2 < 32) load_tiles(nxt2, kt + 2);
        CP_COMMIT();                  // always commit (maybe-empty group)

        const uint32_t* Asb = (const uint32_t*)(sm + cur * GEMM_BUF);
        const uint32_t* Bsb = Asb + 128 * AP;
        #pragma unroll
        for (int ks = 0; ks < 4; ks++) {
            uint32_t af[2][4], bf[8][2];
            #pragma unroll
            for (int mt = 0; mt < 2; mt++) {
                int row = wm * 32 + mt * 16 + gg;
                int c = ks * 8 + tt;
                af[mt][0] = Asb[row * AP + c];
                af[mt][1] = Asb[(row + 8) * AP + c];
                af[mt][2] = Asb[row * AP + c + 4];
                af[mt][3] = Asb[(row + 8) * AP + c + 4];
            }
            #pragma unroll
            for (int nt = 0; nt < 8; nt++) {
                int col = wn * 64 + nt * 8 + gg;
                bf[nt][0] = Bsb[(ks * 8 + tt) * BP + col];
                bf[nt][1] = Bsb[(ks * 8 + tt + 4) * BP + col];
            }
            #pragma unroll
            for (int mt = 0; mt < 2; mt++)
                #pragma unroll
                for (int nt = 0; nt < 8; nt++)
                    mma8(acc[mt][nt], af[mt], bf[nt]);
        }
        cur = (cur + 1 == 3) ? 0 : cur + 1;
        nxt2 = (nxt2 + 1 == 3) ? 0 : nxt2 + 1;
    }

    // epilogue
    #pragma unroll
    for (int mt = 0; mt < 2; mt++) {
        int m0 = bm + wm * 32 + mt * 16;
        #pragma unroll
        for (int nt = 0; nt < 8; nt++) {
            int col = bn + wn * 64 + nt * 8 + 2 * tt;
            float b0v = bias[col], b1v = bias[col + 1];
            #pragma unroll
            for (int half = 0; half < 2; half++) {
                int m = m0 + gg + half * 8;
                float v0 = acc[mt][nt][half * 2 + 0] + b0v;
                float v1 = acc[mt][nt][half * 2 + 1] + b1v;
                if (mode != 0) {
                    if (mode == 2) { v0 *= QSCALE; v1 *= QSCALE; }
                    v0 = cvt_tf32f(v0); v1 = cvt_tf32f(v1);
                    int bb = m >> 11, t = m & (T_ - 1);
                    int h = col >> 6, d = col & 63;
                    *(float2*)&Cout[(((size_t)bb * H_ + h) * T_ + t) * HD_ + d] =
                        make_float2(v0, v1);
                } else {
                    *(float2*)&Cout[(size_t)m * C_ + col] = make_float2(v0, v1);
                }
            }
        }
    }
}

// ============================================================================
// Flash attention (causal), tf32 mma, exp2-domain softmax (Q pre-scaled).
// Block: 128 queries. 8 warps x 16 q-rows. KV 64-key tiles, 3-stage cp.async.
// Longest blocks scheduled first.
// ============================================================================
#define QP 68
#define KVP 68
#define SM_PQ 0
#define SM_KV (128 * QP)                   // 8704 floats
#define KV_TILE (64 * KVP)                 // 4352 floats
#define KVSTRIDE (2 * KV_TILE)             // K+V per buffer = 8704 floats
#define ATTN_SM ((SM_KV + 3 * KVSTRIDE) * 4)   // 139264 bytes

__global__ __launch_bounds__(256, 1) void attn_tc(
    const float* __restrict__ Q, const float* __restrict__ K,
    const float* __restrict__ V, float* __restrict__ Y)
{
    extern __shared__ float sm[];
    uint32_t smb = smem_u32(sm);
    int tid = threadIdx.x, lane = tid & 31, w = tid >> 5;
    int gg = lane >> 2, tt = lane & 3;
    int qt = (gridDim.x - 1) - blockIdx.x;      // longest-first
    int h = blockIdx.y, b = blockIdx.z;
    size_t headbase = ((size_t)b * H_ + h) * T_;
    const float* Qg = Q + (headbase + (size_t)qt * 128) * HD_;

    auto load_kv = [&](int bsel, int kt) {
        uint32_t kb = smb + (uint32_t)(SM_KV + bsel * KVSTRIDE) * 4;
        uint32_t vb = kb + KV_TILE * 4;
        const float* Kg = K + (headbase + (size_t)kt * 64) * HD_;
        const float* Vg = V + (headbase + (size_t)kt * 64) * HD_;
        #pragma unroll
        for (int i = 0; i < 4; i++) {
            int idx = tid + i * 256;
            int r = idx >> 4, s = (idx & 15) * 4;
            cp16(kb + (uint32_t)(r * KVP + s) * 4, Kg + r * HD_ + s);
            cp16(vb + (uint32_t)(r * KVP + s) * 4, Vg + r * HD_ + s);
        }
    };

    int ktmax = 2 * qt + 1;

    // fill Qs; prefetch KV tiles 0,1
    #pragma unroll
    for (int i = 0; i < 8; i++) {
        int idx = tid + i * 256;
        int r = idx >> 4, s = (idx & 15) * 4;
        *(float4*)&sm[SM_PQ + r * QP + s] = *(const float4*)&Qg[r * HD_ + s];
    }
    load_kv(0, 0); CP_COMMIT();
    load_kv(1, 1); CP_COMMIT();
    __syncthreads();

    uint32_t qf[8][4];
    {
        const uint32_t* Qs = (const uint32_t*)&sm[SM_PQ];
        #pragma unroll
        for (int ks = 0; ks < 8; ks++) {
            int row = w * 16 + gg;
            int c = ks * 8 + tt;
            qf[ks][0] = Qs[row * QP + c];
            qf[ks][1] = Qs[(row + 8) * QP + c];
            qf[ks][2] = Qs[row * QP + c + 4];
            qf[ks][3] = Qs[(row + 8) * QP + c + 4];
        }
    }
    __syncthreads();   // Qs region becomes per-warp P staging

    float o[8][4];
    #pragma unroll
    for (int dt = 0; dt < 8; dt++)
        #pragma unroll
        for (int j = 0; j < 4; j++) o[dt][j] = 0.f;
    float mA = -1e30f, mB = -1e30f, lA = 0.f, lB = 0.f;
    int q0w = qt * 128 + w * 16;
    int r0 = q0w + gg, r1 = r0 + 8;
    uint32_t* Ps32 = (uint32_t*)&sm[SM_PQ + w * 16 * QP];

    int cur = 0, nxt2 = 2;
    for (int kt = 0; kt <= ktmax; kt++) {
        CP_WAIT1();
        __syncthreads();
        if (kt + 2 <= ktmax) load_kv(nxt2, kt + 2);
        CP_COMMIT();

        bool active = (kt * 64) <= (q0w + 15);
        if (active) {
            const uint32_t* Ks = (const uint32_t*)&sm[SM_KV + cur * KVSTRIDE];
            const uint32_t* Vs = Ks + KV_TILE;

            // S = Q K^T  (already scaled: log2 domain)
            float s[8][4];
            #pragma unroll
            for (int nt = 0; nt < 8; nt++)
                #pragma unroll
                for (int j = 0; j < 4; j++) s[nt][j] = 0.f;
            #pragma unroll
            for (int ks = 0; ks < 8; ks++) {
                #pragma unroll
                for (int nt = 0; nt < 8; nt++) {
                    uint32_t bv[2];
                    int row = nt * 8 + gg, c = ks * 8 + tt;
                    bv[0] = Ks[row * KVP + c];
                    bv[1] = Ks[row * KVP + c + 4];
                    mma8(s[nt], qf[ks], bv);
                }
            }

            // causal mask
            if ((kt * 64 + 63) > q0w) {
                #pragma unroll
                for (int nt = 0; nt < 8; nt++) {
                    int c0 = kt * 64 + nt * 8 + 2 * tt;
                    if (c0     > r0) s[nt][0] = -1e30f;
                    if (c0 + 1 > r0) s[nt][1] = -1e30f;
                    if (c0     > r1) s[nt][2] = -1e30f;
                    if (c0 + 1 > r1) s[nt][3] = -1e30f;
                }
            }

            // online softmax, base-2
            float tmA = -1e30f, tmB = -1e30f;
            #pragma unroll
            for (int nt = 0; nt < 8; nt++) {
                tmA = fmaxf(tmA, fmaxf(s[nt][0], s[nt][1]));
                tmB = fmaxf(tmB, fmaxf(s[nt][2], s[nt][3]));
            }
            tmA = fmaxf(tmA, __shfl_xor_sync(0xffffffffu, tmA, 1));
            tmA = fmaxf(tmA, __shfl_xor_sync(0xffffffffu, tmA, 2));
            tmB = fmaxf(tmB, __shfl_xor_sync(0xffffffffu, tmB, 1));
            tmB = fmaxf(tmB, __shfl_xor_sync(0xffffffffu, tmB, 2));
            float nmA = fmaxf(mA, tmA), nmB = fmaxf(mB, tmB);
            float cA = exp2f(mA - nmA), cB = exp2f(mB - nmB);
            mA = nmA; mB = nmB;
            float sA = 0.f, sB = 0.f;
            #pragma unroll
            for (int nt = 0; nt < 8; nt++) {
                s[nt][0] = exp2f(s[nt][0] - nmA);
                s[nt][1] = exp2f(s[nt][1] - nmA);
                s[nt][2] = exp2f(s[nt][2] - nmB);
                s[nt][3] = exp2f(s[nt][3] - nmB);
                sA += s[nt][0] + s[nt][1];
                sB += s[nt][2] + s[nt][3];
            }
            sA += __shfl_xor_sync(0xffffffffu, sA, 1);
            sA += __shfl_xor_sync(0xffffffffu, sA, 2);
            sB += __shfl_xor_sync(0xffffffffu, sB, 1);
            sB += __shfl_xor_sync(0xffffffffu, sB, 2);
            lA = lA * cA + sA;
            lB = lB * cB + sB;
            #pragma unroll
            for (int dt = 0; dt < 8; dt++) {
                o[dt][0] *= cA; o[dt][1] *= cA;
                o[dt][2] *= cB; o[dt][3] *= cB;
            }

            // stage P (tf32-rounded) in per-warp smem
            #pragma unroll
            for (int nt = 0; nt < 8; nt++) {
                int colb = nt * 8 + 2 * tt;
                *(uint2*)&Ps32[gg * QP + colb] =
                    make_uint2(cvt_tf32(s[nt][0]), cvt_tf32(s[nt][1]));
                *(uint2*)&Ps32[(gg + 8) * QP + colb] =
                    make_uint2(cvt_tf32(s[nt][2]), cvt_tf32(s[nt][3]));
            }
            __syncwarp();

            // O += P V
            #pragma unroll
            for (int ks = 0; ks < 8; ks++) {
                uint32_t pa[4];
                int c = ks * 8 + tt;
                pa[0] = Ps32[gg * QP + c];
                pa[1] = Ps32[(gg + 8) * QP + c];
                pa[2] = Ps32[gg * QP + c + 4];
                pa[3] = Ps32[(gg + 8) * QP + c + 4];
                #pragma unroll
                for (int dt = 0; dt < 8; dt++) {
                    uint32_t bv[2];
                    bv[0] = Vs[(ks * 8 + tt) * KVP + dt * 8 + gg];
                    bv[1] = Vs[(ks * 8 + tt + 4) * KVP + dt * 8 + gg];
                    mma8(o[dt], pa, bv);
                }
            }
            __syncwarp();
        }
        cur = (cur + 1 == 3) ? 0 : cur + 1;
        nxt2 = (nxt2 + 1 == 3) ? 0 : nxt2 + 1;
    }

    // epilogue: Y[b][q][h*64+d], tf32-rounded (feeds final GEMM)
    float iA = 1.f / lA, iB = 1.f / lB;
    size_t yrowA = ((size_t)b * T_ + q0w + gg) * C_ + h * HD_;
    size_t yrowB = yrowA + (size_t)8 * C_;
    #pragma unroll
    for (int dt = 0; dt < 8; dt++) {
        int col = dt * 8 + 2 * tt;
        *(float2*)&Y[yrowA + col] =
            make_float2(cvt_tf32f(o[dt][0] * iA), cvt_tf32f(o[dt][1] * iA));
        *(float2*)&Y[yrowB + col] =
            make_float2(cvt_tf32f(o[dt][2] * iB), cvt_tf32f(o[dt][3] * iB));
    }
}

// ----------------------------------------------------------------------------
extern "C" void kernel_launch(void* const* d_in, const int* in_sizes, int n_in,
                              void* d_out, int out_size)
{
    const float* x  = (const float*)d_in[0];
    const float* Wq = (const float*)d_in[1];
    const float* bq = (const float*)d_in[2];
    const float* Wk = (const float*)d_in[3];
    const float* bk = (const float*)d_in[4];
    const float* Wv = (const float*)d_in[5];
    const float* bv = (const float*)d_in[6];
    const float* Wp = (const float*)d_in[7];
    const float* bp = (const float*)d_in[8];

    float *Xp, *Wp4, *Qp, *Kp, *Vp, *Yp;
    cudaGetSymbolAddress((void**)&Xp, g_X);
    cudaGetSymbolAddress((void**)&Wp4, g_W4);
    cudaGetSymbolAddress((void**)&Qp, g_Q);
    cudaGetSymbolAddress((void**)&Kp, g_K);
    cudaGetSymbolAddress((void**)&Vp, g_V);
    cudaGetSymbolAddress((void**)&Yp, g_Y);

    cudaFuncSetAttribute(gemm_tc, cudaFuncAttributeMaxDynamicSharedMemorySize, GSM);
    cudaFuncSetAttribute(attn_tc, cudaFuncAttributeMaxDynamicSharedMemorySize, ATTN_SM);

    // fused tf32 pre-round of x + all four W's
    long total4 = (long)N4X + 4L * N4W;   // 2M float4
    round_all_k<<<(int)((total4 + 255) / 256), 256>>>(
        (const float4*)x, (float4*)Xp,
        (const float4*)Wq, (const float4*)Wk, (const float4*)Wv, (const float4*)Wp,
        (float4*)Wp4);

    // fused Q/K/V projections (z = 0,1,2); Q epilogue folds 0.125*log2(e)
    dim3 ggrid(C_ / 128, M_ / 128, 3);
    gemm_tc<<<ggrid, 256, GSM>>>(Xp,
        Wp4 + 0 * C_ * C_, Wp4 + 1 * C_ * C_, Wp4 + 2 * C_ * C_,
        bq, bk, bv, Qp, Kp, Vp, 2);

    attn_tc<<<dim3(T_ / 128, H_, B_), 256, ATTN_SM>>>(Qp, Kp, Vp, Yp);

    // output projection
    dim3 pgrid(C_ / 128, M_ / 128, 1);
    gemm_tc<<<pgrid, 256, GSM>>>(Yp,
        Wp4 + 3 * C_ * C_, Wp4 + 3 * C_ * C_, Wp4 + 3 * C_ * C_,
        bp, bp, bp, (float*)d_out, (float*)d_out, (float*)d_out, 0);
}

// round 5
// speedup vs baseline: 3.8538x; 1.1117x over previous
#include <cuda_runtime.h>
#include <math.h>
#include <stdint.h>

#define B_  2
#define T_  2048
#define C_  1024
#define H_  16
#define HD_ 64
#define M_  (B_*T_)

// Scratch (device globals: allocation-free)
__device__ float g_X[M_*C_];          // tf32-rounded x
__device__ float g_W4[4*C_*C_];       // tf32-rounded Wq,Wk,Wv,Wp
__device__ float g_Q[B_*H_*T_*HD_];   // pre-scaled by 0.125*log2(e), [B,H,T,HD]
__device__ float g_K[B_*H_*T_*HD_];   // [B,H,T,HD]
__device__ float g_V[B_*H_*T_*HD_];   // TRANSPOSED: [B,H,HD,T]
__device__ float g_Y[M_*C_];

#define QSCALE 0.1803368801111731f    /* 0.125 * log2(e) */

// ============================================================================
// helpers (baseline PTX ISA only: mma.sync + cp.async + ldmatrix)
// ============================================================================
__device__ __forceinline__ uint32_t smem_u32(const void* p) {
    uint32_t a;
    asm("{ .reg .u64 t; cvta.to.shared.u64 t, %1; cvt.u32.u64 %0, t; }" : "=r"(a) : "l"(p));
    return a;
}
__device__ __forceinline__ uint32_t cvt_tf32(float x) {
    uint32_t r; asm("cvt.rna.tf32.f32 %0, %1;" : "=r"(r) : "f"(x)); return r;
}
__device__ __forceinline__ float cvt_tf32f(float x) { return __uint_as_float(cvt_tf32(x)); }

__device__ __forceinline__ void cp16(uint32_t dst, const void* src) {
    asm volatile("cp.async.ca.shared.global [%0], [%1], 16;" :: "r"(dst), "l"(src));
}
#define CP_COMMIT() asm volatile("cp.async.commit_group;")
#define CP_WAIT1()  asm volatile("cp.async.wait_group 1;")

// m16n8k8 tf32 mma: A row-major (4 regs), B col-major (2 regs), C f32 (4 regs)
__device__ __forceinline__ void mma8(float* c, const uint32_t* a, const uint32_t* b) {
    asm volatile(
        "mma.sync.aligned.m16n8k8.row.col.f32.tf32.tf32.f32 "
        "{%0,%1,%2,%3}, {%4,%5,%6,%7}, {%8,%9}, {%0,%1,%2,%3};"
        : "+f"(c[0]), "+f"(c[1]), "+f"(c[2]), "+f"(c[3])
        : "r"(a[0]), "r"(a[1]), "r"(a[2]), "r"(a[3]), "r"(b[0]), "r"(b[1]));
}
// ldmatrix x4 (four 8x8 b16 tiles == four 8x4 tf32 tiles)
__device__ __forceinline__ void ldsm4(uint32_t* r, uint32_t addr) {
    asm volatile("ldmatrix.sync.aligned.m8n8.x4.shared.b16 {%0,%1,%2,%3}, [%4];"
                 : "=r"(r[0]), "=r"(r[1]), "=r"(r[2]), "=r"(r[3]) : "r"(addr));
}

// ============================================================================
// fused tf32 pre-round: segment 0 = x, 1..4 = W's
// ============================================================================
#define N4X (M_*C_/4)
#define N4W (C_*C_/4)
__global__ void round_all_k(const float4* __restrict__ x, float4* __restrict__ X,
                            const float4* __restrict__ w0, const float4* __restrict__ w1,
                            const float4* __restrict__ w2, const float4* __restrict__ w3,
                            float4* __restrict__ W4)
{
    long i = (long)blockIdx.x * blockDim.x + threadIdx.x;
    const float4* src; float4* dst;
    if (i < N4X) { src = x + i; dst = X + i; }
    else {
        long j = i - N4X;
        int seg = (int)(j >> 18);
        long off = j & (N4W - 1);
        const float4* ws[4] = {w0, w1, w2, w3};
        src = ws[seg] + off;
        dst = W4 + (long)seg * N4W + off;
    }
    float4 v = *src;
    v.x = cvt_tf32f(v.x); v.y = cvt_tf32f(v.y);
    v.z = cvt_tf32f(v.z); v.w = cvt_tf32f(v.w);
    *dst = v;
}

// ============================================================================
// GEMM (tf32 mma): 128x128 block tile, 8 warps as 2m x 4n of 64x32 warp tiles.
// A-fragments via ldmatrix.x4; k-tile 32; 3-stage cp.async, one sync/k-tile.
// mode: 0 plain f32 [M,C]; 1 head-scatter [B,H,T,HD]+round; 2 = 1 + QSCALE;
// 3 head-scatter TRANSPOSED [B,H,HD,T]+round (for V).
// ============================================================================
#define AP 36
#define BP 136
#define GEMM_BUF (128*AP + 32*BP)           // 8960 floats per buffer
#define GSM (3 * GEMM_BUF * 4)              // 107520 bytes

__global__ __launch_bounds__(256) void gemm_tc(
    const float* __restrict__ A,
    const float* __restrict__ W0, const float* __restrict__ W1, const float* __restrict__ W2,
    const float* __restrict__ b0, const float* __restrict__ b1, const float* __restrict__ b2,
    float* __restrict__ D0, float* __restrict__ D1, float* __restrict__ D2,
    int mode0)
{
    extern __shared__ float sm[];
    uint32_t smb = smem_u32(sm);
    int tid = threadIdx.x, lane = tid & 31, wid = tid >> 5;
    int wm = wid & 1, wn = wid >> 1;          // 2 x 4 warps, 64x32 each
    int gg = lane >> 2, tt = lane & 3;
    int bm = blockIdx.y * 128, bn = blockIdx.x * 128;
    int z = blockIdx.z;

    const float* W; const float* bias; float* Cout; int mode;
    if (z == 0)      { W = W0; bias = b0; Cout = D0; mode = mode0; }
    else if (z == 1) { W = W1; bias = b1; Cout = D1; mode = 1; }
    else             { W = W2; bias = b2; Cout = D2; mode = 3; }

    float acc[4][4][4];
    #pragma unroll
    for (int mt = 0; mt < 4; mt++)
        #pragma unroll
        for (int nt = 0; nt < 4; nt++)
            #pragma unroll
            for (int j = 0; j < 4; j++) acc[mt][nt][j] = 0.f;

    auto load_tiles = [&](int bsel, int kt) {
        int k0 = kt * 32;
        uint32_t abase = smb + bsel * GEMM_BUF * 4;
        uint32_t bbase = abase + 128 * AP * 4;
        #pragma unroll
        for (int i = 0; i < 4; i++) {
            int idx = tid + i * 256;
            int r = idx >> 3, s = (idx & 7) * 4;
            cp16(abase + (uint32_t)(r * AP + s) * 4, A + (size_t)(bm + r) * C_ + k0 + s);
        }
        #pragma unroll
        for (int i = 0; i < 4; i++) {
            int idx = tid + i * 256;
            int r = idx >> 5, s = (idx & 31) * 4;
            cp16(bbase + (uint32_t)(r * BP + s) * 4, W + (size_t)(k0 + r) * C_ + bn + s);
        }
    };

    load_tiles(0, 0); CP_COMMIT();
    load_tiles(1, 1); CP_COMMIT();

    // ldmatrix lane-address (bytes, relative to A-buffer base):
    // lanes 0-15: row = lane (within 16-row frag), col 0; lanes 16-31: row = lane-16, col +4
    uint32_t a_lane_byte = (uint32_t)(((wm * 64 + (lane & 15)) * AP + (lane >> 4) * 4) * 4);

    int cur = 0, nxt2 = 2;
    for (int kt = 0; kt < 32; kt++) {
        CP_WAIT1();
        __syncthreads();
        if (kt + 2 < 32) load_tiles(nxt2, kt + 2);
        CP_COMMIT();

        uint32_t abase = smb + cur * GEMM_BUF * 4;
        const uint32_t* Bsb = (const uint32_t*)(sm + cur * GEMM_BUF) + 128 * AP;
        #pragma unroll
        for (int ks = 0; ks < 4; ks++) {
            uint32_t af[4][4], bf[4][2];
            #pragma unroll
            for (int mt = 0; mt < 4; mt++)
                ldsm4(af[mt], abase + a_lane_byte + (uint32_t)(mt * 16 * AP + ks * 8) * 4);
            #pragma unroll
            for (int nt = 0; nt < 4; nt++) {
                int col = wn * 32 + nt * 8 + gg;
                bf[nt][0] = Bsb[(ks * 8 + tt) * BP + col];
                bf[nt][1] = Bsb[(ks * 8 + tt + 4) * BP + col];
            }
            #pragma unroll
            for (int mt = 0; mt < 4; mt++)
                #pragma unroll
                for (int nt = 0; nt < 4; nt++)
                    mma8(acc[mt][nt], af[mt], bf[nt]);
        }
        cur = (cur + 1 == 3) ? 0 : cur + 1;
        nxt2 = (nxt2 + 1 == 3) ? 0 : nxt2 + 1;
    }

    // epilogue
    #pragma unroll
    for (int mt = 0; mt < 4; mt++) {
        int m0 = bm + wm * 64 + mt * 16;
        #pragma unroll
        for (int nt = 0; nt < 4; nt++) {
            int col = bn + wn * 32 + nt * 8 + 2 * tt;
            float b0v = bias[col], b1v = bias[col + 1];
            #pragma unroll
            for (int half = 0; half < 2; half++) {
                int m = m0 + gg + half * 8;
                float v0 = acc[mt][nt][half * 2 + 0] + b0v;
                float v1 = acc[mt][nt][half * 2 + 1] + b1v;
                if (mode == 0) {
                    *(float2*)&Cout[(size_t)m * C_ + col] = make_float2(v0, v1);
                } else {
                    if (mode == 2) { v0 *= QSCALE; v1 *= QSCALE; }
                    v0 = cvt_tf32f(v0); v1 = cvt_tf32f(v1);
                    int bb = m >> 11, t = m & (T_ - 1);
                    int h = col >> 6, d = col & 63;
                    if (mode == 3) {   // V: [B,H,HD,T]
                        float* base = &Cout[(((size_t)bb * H_ + h) * HD_ + d) * T_ + t];
                        base[0] = v0; base[T_] = v1;
                    } else {
                        *(float2*)&Cout[(((size_t)bb * H_ + h) * T_ + t) * HD_ + d] =
                            make_float2(v0, v1);
                    }
                }
            }
        }
    }
}

// ============================================================================
// Flash attention (causal), tf32 mma, exp2-domain softmax (Q pre-scaled).
// K/P/V fragments via ldmatrix. V in [B,H,HD,T]. 3-stage cp.async.
// ============================================================================
#define QP 68
#define KVP 68
#define VTP 68
#define SM_PQ 0
#define SM_KV (128 * QP)                   // 8704 floats
#define K_TILE (64 * KVP)                  // 4352 floats
#define KVSTRIDE (2 * K_TILE)              // K + Vt per buffer
#define ATTN_SM ((SM_KV + 3 * KVSTRIDE) * 4)   // 139264 bytes

__global__ __launch_bounds__(256, 1) void attn_tc(
    const float* __restrict__ Q, const float* __restrict__ K,
    const float* __restrict__ V, float* __restrict__ Y)
{
    extern __shared__ float sm[];
    uint32_t smb = smem_u32(sm);
    int tid = threadIdx.x, lane = tid & 31, w = tid >> 5;
    int gg = lane >> 2, tt = lane & 3;
    int qt = (gridDim.x - 1) - blockIdx.x;      // longest-first
    int h = blockIdx.y, b = blockIdx.z;
    size_t headbase = ((size_t)b * H_ + h) * T_;
    const float* Qg = Q + (headbase + (size_t)qt * 128) * HD_;
    const float* Vg = V + headbase * HD_ / T_ * T_;   // == V + ((b*H+h)*HD)*T / ... computed below
    const float* Vh = V + ((size_t)b * H_ + h) * HD_ * T_;

    auto load_kv = [&](int bsel, int kt) {
        uint32_t kb = smb + (uint32_t)(SM_KV + bsel * KVSTRIDE) * 4;
        uint32_t vb = kb + K_TILE * 4;
        const float* Kg = K + (headbase + (size_t)kt * 64) * HD_;
        #pragma unroll
        for (int i = 0; i < 4; i++) {
            int idx = tid + i * 256;
            int r = idx >> 4, s = (idx & 15) * 4;
            cp16(kb + (uint32_t)(r * KVP + s) * 4, Kg + r * HD_ + s);
            // V transposed tile: row = d (64 rows), cols = 64 keys
            cp16(vb + (uint32_t)(r * VTP + s) * 4, Vh + (size_t)r * T_ + kt * 64 + s);
        }
    };

    int ktmax = 2 * qt + 1;

    #pragma unroll
    for (int i = 0; i < 8; i++) {
        int idx = tid + i * 256;
        int r = idx >> 4, s = (idx & 15) * 4;
        *(float4*)&sm[SM_PQ + r * QP + s] = *(const float4*)&Qg[r * HD_ + s];
    }
    load_kv(0, 0); CP_COMMIT();
    load_kv(1, 1); CP_COMMIT();
    __syncthreads();

    uint32_t qf[8][4];
    {
        const uint32_t* Qs = (const uint32_t*)&sm[SM_PQ];
        #pragma unroll
        for (int ks = 0; ks < 8; ks++) {
            int row = w * 16 + gg;
            int c = ks * 8 + tt;
            qf[ks][0] = Qs[row * QP + c];
            qf[ks][1] = Qs[(row + 8) * QP + c];
            qf[ks][2] = Qs[row * QP + c + 4];
            qf[ks][3] = Qs[(row + 8) * QP + c + 4];
        }
    }
    __syncthreads();   // Qs region becomes per-warp P staging

    float o[8][4];
    #pragma unroll
    for (int dt = 0; dt < 8; dt++)
        #pragma unroll
        for (int j = 0; j < 4; j++) o[dt][j] = 0.f;
    float mA = -1e30f, mB = -1e30f, lA = 0.f, lB = 0.f;
    int q0w = qt * 128 + w * 16;
    int r0 = q0w + gg, r1 = r0 + 8;
    uint32_t* Ps32 = (uint32_t*)&sm[SM_PQ + w * 16 * QP];
    uint32_t Psbase = smb + (uint32_t)(SM_PQ + w * 16 * QP) * 4;

    // ldmatrix lane-address components (bytes)
    // B-frag tiles (K and Vt): lanes q=lane>>3, r=lane&7:
    //   row = (q>=2 ? 8 : 0) + r ; col = (q&1)*4
    uint32_t b_row = (uint32_t)(((lane >> 4) * 8) + (lane & 7));
    uint32_t b_col4 = (uint32_t)(((lane >> 3) & 1) * 4);
    uint32_t k_lane_byte = (b_row * KVP + b_col4) * 4;
    uint32_t v_lane_byte = (b_row * VTP + b_col4) * 4;
    // A-frag tiles (P): lanes 0-15 row=lane col0; 16-31 row=lane-16 col4
    uint32_t p_lane_byte = (uint32_t)(((lane & 15) * QP + (lane >> 4) * 4) * 4);

    int cur = 0, nxt2 = 2;
    for (int kt = 0; kt <= ktmax; kt++) {
        CP_WAIT1();
        __syncthreads();
        if (kt + 2 <= ktmax) load_kv(nxt2, kt + 2);
        CP_COMMIT();

        bool active = (kt * 64) <= (q0w + 15);
        if (active) {
            uint32_t Ksb = smb + (uint32_t)(SM_KV + cur * KVSTRIDE) * 4;
            uint32_t Vtb = Ksb + K_TILE * 4;

            // S = Q K^T  (log2 domain)
            float s[8][4];
            #pragma unroll
            for (int nt = 0; nt < 8; nt++)
                #pragma unroll
                for (int j = 0; j < 4; j++) s[nt][j] = 0.f;
            #pragma unroll
            for (int ks = 0; ks < 8; ks++) {
                #pragma unroll
                for (int p = 0; p < 4; p++) {      // nt pair = (2p, 2p+1)
                    uint32_t b4[4];
                    ldsm4(b4, Ksb + k_lane_byte + (uint32_t)((2 * p) * 8 * KVP + ks * 8) * 4);
                    mma8(s[2 * p],     qf[ks], b4);
                    mma8(s[2 * p + 1], qf[ks], b4 + 2);
                }
            }

            // causal mask
            if ((kt * 64 + 63) > q0w) {
                #pragma unroll
                for (int nt = 0; nt < 8; nt++) {
                    int c0 = kt * 64 + nt * 8 + 2 * tt;
                    if (c0     > r0) s[nt][0] = -1e30f;
                    if (c0 + 1 > r0) s[nt][1] = -1e30f;
                    if (c0     > r1) s[nt][2] = -1e30f;
                    if (c0 + 1 > r1) s[nt][3] = -1e30f;
                }
            }

            // online softmax, base-2
            float tmA = -1e30f, tmB = -1e30f;
            #pragma unroll
            for (int nt = 0; nt < 8; nt++) {
                tmA = fmaxf(tmA, fmaxf(s[nt][0], s[nt][1]));
                tmB = fmaxf(tmB, fmaxf(s[nt][2], s[nt][3]));
            }
            tmA = fmaxf(tmA, __shfl_xor_sync(0xffffffffu, tmA, 1));
            tmA = fmaxf(tmA, __shfl_xor_sync(0xffffffffu, tmA, 2));
            tmB = fmaxf(tmB, __shfl_xor_sync(0xffffffffu, tmB, 1));
            tmB = fmaxf(tmB, __shfl_xor_sync(0xffffffffu, tmB, 2));
            float nmA = fmaxf(mA, tmA), nmB = fmaxf(mB, tmB);
            float cA = exp2f(mA - nmA), cB = exp2f(mB - nmB);
            mA = nmA; mB = nmB;
            float sA = 0.f, sB = 0.f;
            #pragma unroll
            for (int nt = 0; nt < 8; nt++) {
                s[nt][0] = exp2f(s[nt][0] - nmA);
                s[nt][1] = exp2f(s[nt][1] - nmA);
                s[nt][2] = exp2f(s[nt][2] - nmB);
                s[nt][3] = exp2f(s[nt][3] - nmB);
                sA += s[nt][0] + s[nt][1];
                sB += s[nt][2] + s[nt][3];
            }
            sA += __shfl_xor_sync(0xffffffffu, sA, 1);
            sA += __shfl_xor_sync(0xffffffffu, sA, 2);
            sB += __shfl_xor_sync(0xffffffffu, sB, 1);
            sB += __shfl_xor_sync(0xffffffffu, sB, 2);
            lA = lA * cA + sA;
            lB = lB * cB + sB;
            #pragma unroll
            for (int dt = 0; dt < 8; dt++) {
                o[dt][0] *= cA; o[dt][1] *= cA;
                o[dt][2] *= cB; o[dt][3] *= cB;
            }

            // stage P (tf32-rounded) in per-warp smem
            #pragma unroll
            for (int nt = 0; nt < 8; nt++) {
                int colb = nt * 8 + 2 * tt;
                *(uint2*)&Ps32[gg * QP + colb] =
                    make_uint2(cvt_tf32(s[nt][0]), cvt_tf32(s[nt][1]));
                *(uint2*)&Ps32[(gg + 8) * QP + colb] =
                    make_uint2(cvt_tf32(s[nt][2]), cvt_tf32(s[nt][3]));
            }
            __syncwarp();

            // O += P V   (P a-frags + Vt b-frags via ldmatrix)
            #pragma unroll
            for (int ks = 0; ks < 8; ks++) {
                uint32_t pa[4];
                ldsm4(pa, Psbase + p_lane_byte + (uint32_t)(ks * 8) * 4);
                #pragma unroll
                for (int p = 0; p < 4; p++) {   // dt pair = (2p, 2p+1)
                    uint32_t v4[4];
                    ldsm4(v4, Vtb + v_lane_byte + (uint32_t)((2 * p) * 8 * VTP + ks * 8) * 4);
                    mma8(o[2 * p],     pa, v4);
                    mma8(o[2 * p + 1], pa, v4 + 2);
                }
            }
            __syncwarp();
        }
        cur = (cur + 1 == 3) ? 0 : cur + 1;
        nxt2 = (nxt2 + 1 == 3) ? 0 : nxt2 + 1;
    }

    // epilogue: Y[b][q][h*64+d], tf32-rounded (feeds final GEMM)
    float iA = 1.f / lA, iB = 1.f / lB;
    size_t yrowA = ((size_t)b * T_ + q0w + gg) * C_ + h * HD_;
    size_t yrowB = yrowA + (size_t)8 * C_;
    #pragma unroll
    for (int dt = 0; dt < 8; dt++) {
        int col = dt * 8 + 2 * tt;
        *(float2*)&Y[yrowA + col] =
            make_float2(cvt_tf32f(o[dt][0] * iA), cvt_tf32f(o[dt][1] * iA));
        *(float2*)&Y[yrowB + col] =
            make_float2(cvt_tf32f(o[dt][2] * iB), cvt_tf32f(o[dt][3] * iB));
    }
}

// ----------------------------------------------------------------------------
extern "C" void kernel_launch(void* const* d_in, const int* in_sizes, int n_in,
                              void* d_out, int out_size)
{
    const float* x  = (const float*)d_in[0];
    const float* Wq = (const float*)d_in[1];
    const float* bq = (const float*)d_in[2];
    const float* Wk = (const float*)d_in[3];
    const float* bk = (const float*)d_in[4];
    const float* Wv = (const float*)d_in[5];
    const float* bv = (const float*)d_in[6];
    const float* Wp = (const float*)d_in[7];
    const float* bp = (const float*)d_in[8];

    float *Xp, *Wp4, *Qp, *Kp, *Vp, *Yp;
    cudaGetSymbolAddress((void**)&Xp, g_X);
    cudaGetSymbolAddress((void**)&Wp4, g_W4);
    cudaGetSymbolAddress((void**)&Qp, g_Q);
    cudaGetSymbolAddress((void**)&Kp, g_K);
    cudaGetSymbolAddress((void**)&Vp, g_V);
    cudaGetSymbolAddress((void**)&Yp, g_Y);

    cudaFuncSetAttribute(gemm_tc, cudaFuncAttributeMaxDynamicSharedMemorySize, GSM);
    cudaFuncSetAttribute(attn_tc, cudaFuncAttributeMaxDynamicSharedMemorySize, ATTN_SM);

    long total4 = (long)N4X + 4L * N4W;
    round_all_k<<<(int)((total4 + 255) / 256), 256>>>(
        (const float4*)x, (float4*)Xp,
        (const float4*)Wq, (const float4*)Wk, (const float4*)Wv, (const float4*)Wp,
        (float4*)Wp4);

    // fused Q/K/V projections (z=0: Q scaled; z=1: K; z=2: V transposed)
    dim3 ggrid(C_ / 128, M_ / 128, 3);
    gemm_tc<<<ggrid, 256, GSM>>>(Xp,
        Wp4 + 0 * C_ * C_, Wp4 + 1 * C_ * C_, Wp4 + 2 * C_ * C_,
        bq, bk, bv, Qp, Kp, Vp, 2);

    attn_tc<<<dim3(T_ / 128, H_, B_), 256, ATTN_SM>>>(Qp, Kp, Vp, Yp);

    dim3 pgrid(C_ / 128, M_ / 128, 1);
    gemm_tc<<<pgrid, 256, GSM>>>(Yp,
        Wp4 + 3 * C_ * C_, Wp4 + 3 * C_ * C_, Wp4 + 3 * C_ * C_,
        bp, bp, bp, (float*)d_out, (float*)d_out, (float*)d_out, 0);
}

// round 6
// speedup vs baseline: 4.5840x; 1.1895x over previous
#include <cuda_runtime.h>
#include <cuda_fp16.h>
#include <math.h>
#include <stdint.h>

#define B_  2
#define T_  2048
#define C_  1024
#define H_  16
#define HD_ 64
#define M_  (B_*T_)

// Scratch (device globals: allocation-free) — all fp16 now
__device__ __half g_X[M_*C_];          // fp16 x
__device__ __half g_W4[4*C_*C_];       // fp16 Wq,Wk,Wv,Wp
__device__ __half g_Q[B_*H_*T_*HD_];   // pre-scaled by 0.125*log2(e), [B,H,T,HD]
__device__ __half g_K[B_*H_*T_*HD_];   // [B,H,T,HD]
__device__ __half g_V[B_*H_*T_*HD_];   // [B,H,T,HD] (natural; PV uses ldmatrix.trans)
__device__ __half g_Y[M_*C_];

#define QSCALE 0.1803368801111731f    /* 0.125 * log2(e) */

// ============================================================================
// helpers (baseline PTX ISA: mma.sync fp16 + cp.async + ldmatrix)
// ============================================================================
__device__ __forceinline__ uint32_t smem_u32(const void* p) {
    uint32_t a;
    asm("{ .reg .u64 t; cvta.to.shared.u64 t, %1; cvt.u32.u64 %0, t; }" : "=r"(a) : "l"(p));
    return a;
}
__device__ __forceinline__ void cp16(uint32_t dst, const void* src) {
    asm volatile("cp.async.ca.shared.global [%0], [%1], 16;" :: "r"(dst), "l"(src));
}
#define CP_COMMIT() asm volatile("cp.async.commit_group;")
#define CP_WAIT1()  asm volatile("cp.async.wait_group 1;")

// m16n8k16 fp16 mma, f32 accumulate
__device__ __forceinline__ void mma16(float* c, const uint32_t* a, const uint32_t* b) {
    asm volatile(
        "mma.sync.aligned.m16n8k16.row.col.f32.f16.f16.f32 "
        "{%0,%1,%2,%3}, {%4,%5,%6,%7}, {%8,%9}, {%0,%1,%2,%3};"
        : "+f"(c[0]), "+f"(c[1]), "+f"(c[2]), "+f"(c[3])
        : "r"(a[0]), "r"(a[1]), "r"(a[2]), "r"(a[3]), "r"(b[0]), "r"(b[1]));
}
__device__ __forceinline__ void ldsm4(uint32_t* r, uint32_t addr) {
    asm volatile("ldmatrix.sync.aligned.m8n8.x4.shared.b16 {%0,%1,%2,%3}, [%4];"
                 : "=r"(r[0]), "=r"(r[1]), "=r"(r[2]), "=r"(r[3]) : "r"(addr));
}
__device__ __forceinline__ void ldsm4t(uint32_t* r, uint32_t addr) {
    asm volatile("ldmatrix.sync.aligned.m8n8.x4.trans.shared.b16 {%0,%1,%2,%3}, [%4];"
                 : "=r"(r[0]), "=r"(r[1]), "=r"(r[2]), "=r"(r[3]) : "r"(addr));
}
__device__ __forceinline__ uint32_t h2u(__half2 h) { return *(uint32_t*)&h; }

// ============================================================================
// fp16 convert: segment 0 = x, 1..4 = W's. Each thread converts 8 floats.
// ============================================================================
#define N8X (M_*C_/8)
#define N8W (C_*C_/8)
__global__ void cvt_all_k(const float4* __restrict__ x,
                          const float4* __restrict__ w0, const float4* __restrict__ w1,
                          const float4* __restrict__ w2, const float4* __restrict__ w3,
                          __half* __restrict__ X, __half* __restrict__ W4)
{
    long i = (long)blockIdx.x * blockDim.x + threadIdx.x;
    const float4* src; __half* dst;
    if (i < N8X) { src = x + 2 * i; dst = X + 8 * i; }
    else {
        long j = i - N8X;
        int seg = (int)(j >> 17);              // / N8W (131072)
        long off = j & (N8W - 1);
        const float4* ws[4] = {w0, w1, w2, w3};
        src = ws[seg] + 2 * off;
        dst = W4 + (long)seg * (C_ * C_) + 8 * off;
    }
    float4 v0 = src[0], v1 = src[1];
    __half h[8];
    h[0] = __float2half_rn(v0.x); h[1] = __float2half_rn(v0.y);
    h[2] = __float2half_rn(v0.z); h[3] = __float2half_rn(v0.w);
    h[4] = __float2half_rn(v1.x); h[5] = __float2half_rn(v1.y);
    h[6] = __float2half_rn(v1.z); h[7] = __float2half_rn(v1.w);
    *(uint4*)dst = *(uint4*)h;
}

// ============================================================================
// GEMM (fp16 mma): 128x128 block tile, 8 warps (2m x 4n, 64x32 each),
// k-tile 32, 3-stage cp.async, A frags ldmatrix, B frags ldmatrix.trans.
// mode: 0 -> f32 out [M,C]; 1 -> fp16 head-scatter [B,H,T,HD]; 2 = 1 + QSCALE.
// ============================================================================
#define APB 80                    // A row pitch bytes (32 fp16 + pad)
#define BPB 272                   // B row pitch bytes (128 fp16 + pad)
#define ABYTES (128*APB)          // 10240
#define BBYTES (32*BPB)           // 8704
#define GBUF (ABYTES + BBYTES)    // 18944
#define GSM (3 * GBUF)            // 56832

__global__ __launch_bounds__(256) void gemm_tc(
    const __half* __restrict__ A,
    const __half* __restrict__ W0, const __half* __restrict__ W1, const __half* __restrict__ W2,
    const float* __restrict__ b0, const float* __restrict__ b1, const float* __restrict__ b2,
    void* __restrict__ D0, void* __restrict__ D1, void* __restrict__ D2,
    int mode0)
{
    extern __shared__ char sm[];
    uint32_t smb = smem_u32(sm);
    int tid = threadIdx.x, lane = tid & 31, wid = tid >> 5;
    int wm = wid & 1, wn = wid >> 1;
    int gg = lane >> 2, tt = lane & 3;
    int bm = blockIdx.y * 128, bn = blockIdx.x * 128;
    int z = blockIdx.z;

    const __half* W; const float* bias; void* Cout; int mode;
    if (z == 0)      { W = W0; bias = b0; Cout = D0; mode = mode0; }
    else if (z == 1) { W = W1; bias = b1; Cout = D1; mode = 1; }
    else             { W = W2; bias = b2; Cout = D2; mode = 1; }

    float acc[4][4][4];
    #pragma unroll
    for (int mt = 0; mt < 4; mt++)
        #pragma unroll
        for (int nt = 0; nt < 4; nt++)
            #pragma unroll
            for (int j = 0; j < 4; j++) acc[mt][nt][j] = 0.f;

    auto load_tiles = [&](int bsel, int kt) {
        int k0 = kt * 32;
        uint32_t abase = smb + bsel * GBUF;
        uint32_t bbase = abase + ABYTES;
        #pragma unroll
        for (int i = 0; i < 2; i++) {          // A: 512 chunks of 16B
            int idx = tid + i * 256;
            int r = idx >> 2, c = idx & 3;
            cp16(abase + (uint32_t)(r * APB + c * 16), A + (size_t)(bm + r) * C_ + k0 + c * 8);
        }
        #pragma unroll
        for (int i = 0; i < 2; i++) {          // B: 512 chunks
            int idx = tid + i * 256;
            int r = idx >> 4, c = idx & 15;
            cp16(bbase + (uint32_t)(r * BPB + c * 16), W + (size_t)(k0 + r) * C_ + bn + c * 8);
        }
    };

    load_tiles(0, 0); CP_COMMIT();
    load_tiles(1, 1); CP_COMMIT();

    uint32_t a_lane_byte = (uint32_t)((wm * 64 + (lane & 15)) * APB + (lane >> 4) * 16);
    uint32_t b_lane_byte = (uint32_t)((lane & 15) * BPB + (lane >> 4) * 16 + wn * 64);

    int cur = 0, nxt2 = 2;
    for (int kt = 0; kt < 32; kt++) {
        CP_WAIT1();
        __syncthreads();
        if (kt + 2 < 32) load_tiles(nxt2, kt + 2);
        CP_COMMIT();

        uint32_t abase = smb + cur * GBUF;
        uint32_t bbase = abase + ABYTES;
        #pragma unroll
        for (int ks = 0; ks < 2; ks++) {
            uint32_t af[4][4];
            #pragma unroll
            for (int mt = 0; mt < 4; mt++)
                ldsm4(af[mt], abase + a_lane_byte + (uint32_t)(mt * 16 * APB + ks * 32));
            #pragma unroll
            for (int g = 0; g < 2; g++) {
                uint32_t b4[4];
                ldsm4t(b4, bbase + b_lane_byte + (uint32_t)(ks * 16 * BPB + g * 32));
                #pragma unroll
                for (int mt = 0; mt < 4; mt++) {
                    mma16(acc[mt][2 * g],     af[mt], b4);
                    mma16(acc[mt][2 * g + 1], af[mt], b4 + 2);
                }
            }
        }
        cur = (cur + 1 == 3) ? 0 : cur + 1;
        nxt2 = (nxt2 + 1 == 3) ? 0 : nxt2 + 1;
    }

    // epilogue
    #pragma unroll
    for (int mt = 0; mt < 4; mt++) {
        int m0 = bm + wm * 64 + mt * 16;
        #pragma unroll
        for (int nt = 0; nt < 4; nt++) {
            int col = bn + wn * 32 + nt * 8 + 2 * tt;
            float b0v = bias[col], b1v = bias[col + 1];
            #pragma unroll
            for (int half = 0; half < 2; half++) {
                int m = m0 + gg + half * 8;
                float v0 = acc[mt][nt][half * 2 + 0] + b0v;
                float v1 = acc[mt][nt][half * 2 + 1] + b1v;
                if (mode == 0) {
                    *(float2*)&((float*)Cout)[(size_t)m * C_ + col] = make_float2(v0, v1);
                } else {
                    if (mode == 2) { v0 *= QSCALE; v1 *= QSCALE; }
                    int bb = m >> 11, t = m & (T_ - 1);
                    int h = col >> 6, d = col & 63;
                    *(__half2*)&((__half*)Cout)[(((size_t)bb * H_ + h) * T_ + t) * HD_ + d] =
                        __floats2half2_rn(v0, v1);
                }
            }
        }
    }
}

// ============================================================================
// Flash attention (causal), fp16 mma, exp2-domain softmax (Q pre-scaled).
// K frags: ldmatrix from [n][d]; V frags: ldmatrix.trans from [k][d];
// P staged half2 per-warp. 3-stage cp.async KV pipeline.
// ============================================================================
#define QPB 144                        // Q/P row pitch bytes (64 fp16 + pad)
#define KPB 144                        // K/V row pitch bytes
#define QBYTES (128 * QPB)             // 18432
#define KTILEB (64 * KPB)              // 9216
#define KVBUF (2 * KTILEB)             // 18432
#define ATTN_SM (QBYTES + 3 * KVBUF)   // 73728

__global__ __launch_bounds__(256, 1) void attn_tc(
    const __half* __restrict__ Q, const __half* __restrict__ K,
    const __half* __restrict__ V, __half* __restrict__ Y)
{
    extern __shared__ char sm[];
    uint32_t smb = smem_u32(sm);
    int tid = threadIdx.x, lane = tid & 31, w = tid >> 5;
    int gg = lane >> 2, tt = lane & 3;
    int qt = (gridDim.x - 1) - blockIdx.x;      // longest-first
    int h = blockIdx.y, b = blockIdx.z;
    size_t headbase = ((size_t)b * H_ + h) * T_;
    const __half* Qg = Q + (headbase + (size_t)qt * 128) * HD_;

    auto load_kv = [&](int bsel, int kt) {
        uint32_t kb = smb + QBYTES + bsel * KVBUF;
        uint32_t vb = kb + KTILEB;
        const __half* Kg = K + (headbase + (size_t)kt * 64) * HD_;
        const __half* Vg = V + (headbase + (size_t)kt * 64) * HD_;
        #pragma unroll
        for (int i = 0; i < 2; i++) {
            int idx = tid + i * 256;
            int r = idx >> 3, c = idx & 7;
            cp16(kb + (uint32_t)(r * KPB + c * 16), Kg + r * HD_ + c * 8);
            cp16(vb + (uint32_t)(r * KPB + c * 16), Vg + r * HD_ + c * 8);
        }
    };

    int ktmax = 2 * qt + 1;

    // Q -> smem (plain loads), prefetch KV 0,1
    load_kv(0, 0); CP_COMMIT();
    load_kv(1, 1); CP_COMMIT();
    #pragma unroll
    for (int i = 0; i < 4; i++) {
        int idx = tid + i * 256;
        int r = idx >> 3, c = idx & 7;
        *(uint4*)(sm + r * QPB + c * 16) = *(const uint4*)&Qg[r * HD_ + c * 8];
    }
    __syncthreads();

    // Q fragments: 4 k-steps of 16
    uint32_t qf[4][4];
    uint32_t q_lane_byte = (uint32_t)((w * 16 + (lane & 15)) * QPB + (lane >> 4) * 16);
    #pragma unroll
    for (int ks = 0; ks < 4; ks++)
        ldsm4(qf[ks], smb + q_lane_byte + (uint32_t)(ks * 32));
    __syncthreads();   // Q region becomes per-warp P staging

    float o[8][4];
    #pragma unroll
    for (int dt = 0; dt < 8; dt++)
        #pragma unroll
        for (int j = 0; j < 4; j++) o[dt][j] = 0.f;
    float mA = -1e30f, mB = -1e30f, lA = 0.f, lB = 0.f;
    int q0w = qt * 128 + w * 16;
    int r0 = q0w + gg, r1 = r0 + 8;
    char* Psc = sm + w * 16 * QPB;
    uint32_t Psbase = smb + (uint32_t)(w * 16 * QPB);

    // lane address components
    uint32_t k_lane_byte = (uint32_t)(((lane >> 4) * 8 + (lane & 7)) * KPB + ((lane >> 3) & 1) * 16);
    uint32_t v_lane_byte = (uint32_t)((lane & 15) * KPB + (lane >> 4) * 16);
    uint32_t p_lane_byte = (uint32_t)((lane & 15) * QPB + (lane >> 4) * 16);

    int cur = 0, nxt2 = 2;
    for (int kt = 0; kt <= ktmax; kt++) {
        CP_WAIT1();
        __syncthreads();
        if (kt + 2 <= ktmax) load_kv(nxt2, kt + 2);
        CP_COMMIT();

        bool active = (kt * 64) <= (q0w + 15);
        if (active) {
            uint32_t Ksb = smb + QBYTES + cur * KVBUF;
            uint32_t Vtb = Ksb + KTILEB;

            // S = Q K^T (log2 domain)
            float s[8][4];
            #pragma unroll
            for (int nt = 0; nt < 8; nt++)
                #pragma unroll
                for (int j = 0; j < 4; j++) s[nt][j] = 0.f;
            #pragma unroll
            for (int ks = 0; ks < 4; ks++) {
                #pragma unroll
                for (int np = 0; np < 4; np++) {
                    uint32_t b4[4];
                    ldsm4(b4, Ksb + k_lane_byte + (uint32_t)(np * 16 * KPB + ks * 32));
                    mma16(s[2 * np],     qf[ks], b4);
                    mma16(s[2 * np + 1], qf[ks], b4 + 2);
                }
            }

            // causal mask
            if ((kt * 64 + 63) > q0w) {
                #pragma unroll
                for (int nt = 0; nt < 8; nt++) {
                    int c0 = kt * 64 + nt * 8 + 2 * tt;
                    if (c0     > r0) s[nt][0] = -1e30f;
                    if (c0 + 1 > r0) s[nt][1] = -1e30f;
                    if (c0     > r1) s[nt][2] = -1e30f;
                    if (c0 + 1 > r1) s[nt][3] = -1e30f;
                }
            }

            // online softmax, base-2
            float tmA = -1e30f, tmB = -1e30f;
            #pragma unroll
            for (int nt = 0; nt < 8; nt++) {
                tmA = fmaxf(tmA, fmaxf(s[nt][0], s[nt][1]));
                tmB = fmaxf(tmB, fmaxf(s[nt][2], s[nt][3]));
            }
            tmA = fmaxf(tmA, __shfl_xor_sync(0xffffffffu, tmA, 1));
            tmA = fmaxf(tmA, __shfl_xor_sync(0xffffffffu, tmA, 2));
            tmB = fmaxf(tmB, __shfl_xor_sync(0xffffffffu, tmB, 1));
            tmB = fmaxf(tmB, __shfl_xor_sync(0xffffffffu, tmB, 2));
            float nmA = fmaxf(mA, tmA), nmB = fmaxf(mB, tmB);
            float cA = exp2f(mA - nmA), cB = exp2f(mB - nmB);
            mA = nmA; mB = nmB;
            float sA = 0.f, sB = 0.f;
            #pragma unroll
            for (int nt = 0; nt < 8; nt++) {
                s[nt][0] = exp2f(s[nt][0] - nmA);
                s[nt][1] = exp2f(s[nt][1] - nmA);
                s[nt][2] = exp2f(s[nt][2] - nmB);
                s[nt][3] = exp2f(s[nt][3] - nmB);
                sA += s[nt][0] + s[nt][1];
                sB += s[nt][2] + s[nt][3];
            }
            sA += __shfl_xor_sync(0xffffffffu, sA, 1);
            sA += __shfl_xor_sync(0xffffffffu, sA, 2);
            sB += __shfl_xor_sync(0xffffffffu, sB, 1);
            sB += __shfl_xor_sync(0xffffffffu, sB, 2);
            lA = lA * cA + sA;
            lB = lB * cB + sB;
            #pragma unroll
            for (int dt = 0; dt < 8; dt++) {
                o[dt][0] *= cA; o[dt][1] *= cA;
                o[dt][2] *= cB; o[dt][3] *= cB;
            }

            // stage P (fp16) in per-warp smem
            #pragma unroll
            for (int nt = 0; nt < 8; nt++) {
                int colb = (nt * 8 + 2 * tt) * 2;
                *(uint32_t*)(Psc + gg * QPB + colb)       = h2u(__floats2half2_rn(s[nt][0], s[nt][1]));
                *(uint32_t*)(Psc + (gg + 8) * QPB + colb) = h2u(__floats2half2_rn(s[nt][2], s[nt][3]));
            }
            __syncwarp();

            // O += P V  (P a-frags ldmatrix; V b-frags ldmatrix.trans)
            #pragma unroll
            for (int ks = 0; ks < 4; ks++) {
                uint32_t pa[4];
                ldsm4(pa, Psbase + p_lane_byte + (uint32_t)(ks * 32));
                #pragma unroll
                for (int dp = 0; dp < 4; dp++) {
                    uint32_t v4[4];
                    ldsm4t(v4, Vtb + v_lane_byte + (uint32_t)(ks * 16 * KPB + dp * 32));
                    mma16(o[2 * dp],     pa, v4);
                    mma16(o[2 * dp + 1], pa, v4 + 2);
                }
            }
            __syncwarp();
        }
        cur = (cur + 1 == 3) ? 0 : cur + 1;
        nxt2 = (nxt2 + 1 == 3) ? 0 : nxt2 + 1;
    }

    // epilogue: Y (fp16) [b][q][h*64+d]
    float iA = 1.f / lA, iB = 1.f / lB;
    size_t yrowA = ((size_t)b * T_ + q0w + gg) * C_ + h * HD_;
    size_t yrowB = yrowA + (size_t)8 * C_;
    #pragma unroll
    for (int dt = 0; dt < 8; dt++) {
        int col = dt * 8 + 2 * tt;
        *(__half2*)&Y[yrowA + col] = __floats2half2_rn(o[dt][0] * iA, o[dt][1] * iA);
        *(__half2*)&Y[yrowB + col] = __floats2half2_rn(o[dt][2] * iB, o[dt][3] * iB);
    }
}

// ----------------------------------------------------------------------------
extern "C" void kernel_launch(void* const* d_in, const int* in_sizes, int n_in,
                              void* d_out, int out_size)
{
    const float* x  = (const float*)d_in[0];
    const float* Wq = (const float*)d_in[1];
    const float* bq = (const float*)d_in[2];
    const float* Wk = (const float*)d_in[3];
    const float* bk = (const float*)d_in[4];
    const float* Wv = (const float*)d_in[5];
    const float* bv = (const float*)d_in[6];
    const float* Wp = (const float*)d_in[7];
    const float* bp = (const float*)d_in[8];

    __half *Xp, *Wp4, *Qp, *Kp, *Vp, *Yp;
    cudaGetSymbolAddress((void**)&Xp, g_X);
    cudaGetSymbolAddress((void**)&Wp4, g_W4);
    cudaGetSymbolAddress((void**)&Qp, g_Q);
    cudaGetSymbolAddress((void**)&Kp, g_K);
    cudaGetSymbolAddress((void**)&Vp, g_V);
    cudaGetSymbolAddress((void**)&Yp, g_Y);

    cudaFuncSetAttribute(gemm_tc, cudaFuncAttributeMaxDynamicSharedMemorySize, GSM);
    cudaFuncSetAttribute(attn_tc, cudaFuncAttributeMaxDynamicSharedMemorySize, ATTN_SM);

    long total8 = (long)N8X + 4L * N8W;    // 1,048,576 threads
    cvt_all_k<<<(int)((total8 + 255) / 256), 256>>>(
        (const float4*)x,
        (const float4*)Wq, (const float4*)Wk, (const float4*)Wv, (const float4*)Wp,
        Xp, Wp4);

    // fused Q/K/V projections (z=0: Q with QSCALE; z=1: K; z=2: V)
    dim3 ggrid(C_ / 128, M_ / 128, 3);
    gemm_tc<<<ggrid, 256, GSM>>>(Xp,
        Wp4 + 0 * C_ * C_, Wp4 + 1 * C_ * C_, Wp4 + 2 * C_ * C_,
        bq, bk, bv, Qp, Kp, Vp, 2);

    attn_tc<<<dim3(T_ / 128, H_, B_), 256, ATTN_SM>>>(Qp, Kp, Vp, Yp);

    // output projection -> f32 d_out
    dim3 pgrid(C_ / 128, M_ / 128, 1);
    gemm_tc<<<pgrid, 256, GSM>>>(Yp,
        Wp4 + 3 * C_ * C_, Wp4 + 3 * C_ * C_, Wp4 + 3 * C_ * C_,
        bp, bp, bp, d_out, d_out, d_out, 0);
}